// round 8
// baseline (speedup 1.0000x reference)
#include <cuda_runtime.h>
#include <cuda_bf16.h>
#include <float.h>
#include <stdint.h>

#define MAX_N 8192
#define N_CLASSES 1024
#define BLOCK 256
#define CHUNKS 8
#define CHUNK_FLOATS 1024            // 4 KB per chunk
#define CHUNK_BYTES 4096
#define GRID MAX_N                   // one block per row

// Per-(class, tid) mask word: bit (chunk*4+e) = targets[chunk*1024+tid*4+e]==class
__device__ unsigned int g_mask32[N_CLASSES * BLOCK];
__device__ float        g_block_sum[GRID];
__device__ unsigned int g_done_count = 0;   // self-resets via atomicInc wrap

__global__ __launch_bounds__(BLOCK)
void build_masks_kernel(const int* __restrict__ targets) {
    const int c   = blockIdx.x;
    const int tid = threadIdx.x;
    const int4* __restrict__ tp = reinterpret_cast<const int4*>(targets);
    unsigned int word = 0;
    #pragma unroll
    for (int ch = 0; ch < CHUNKS; ch++) {
        const int4 t = tp[(ch * CHUNK_FLOATS + tid * 4) >> 2];
        unsigned int nib = (unsigned)(t.x == c) | ((unsigned)(t.y == c) << 1)
                         | ((unsigned)(t.z == c) << 2) | ((unsigned)(t.w == c) << 3);
        word |= nib << (ch * 4);
    }
    g_mask32[c * BLOCK + tid] = word;
}

__device__ __forceinline__ uint32_t smem_addr_u32(const void* p) {
    uint32_t a;
    asm("{ .reg .u64 t; cvta.to.shared.u64 t, %1; cvt.u32.u64 %0, t; }"
        : "=r"(a) : "l"(p));
    return a;
}

__device__ __forceinline__ void mbar_init(uint32_t mbar, uint32_t cnt) {
    asm volatile("mbarrier.init.shared.b64 [%0], %1;" :: "r"(mbar), "r"(cnt) : "memory");
}
__device__ __forceinline__ void mbar_expect_tx(uint32_t mbar, uint32_t bytes) {
    asm volatile("mbarrier.arrive.expect_tx.shared.b64 _, [%0], %1;"
                 :: "r"(mbar), "r"(bytes) : "memory");
}
__device__ __forceinline__ void bulk_g2s(uint32_t dst, const void* src,
                                         uint32_t bytes, uint32_t mbar) {
    asm volatile("cp.async.bulk.shared::cta.global.mbarrier::complete_tx::bytes "
                 "[%0], [%1], %2, [%3];"
                 :: "r"(dst), "l"(src), "r"(bytes), "r"(mbar) : "memory");
}
__device__ __forceinline__ void mbar_wait(uint32_t mbar, uint32_t parity) {
    uint32_t done;
    asm volatile("{\n\t.reg .pred p;\n\t"
                 "mbarrier.try_wait.parity.acquire.cta.shared::cta.b64 p, [%1], %2;\n\t"
                 "selp.b32 %0, 1, 0, p;\n\t}"
                 : "=r"(done) : "r"(mbar), "r"(parity) : "memory");
    if (!done) {
        asm volatile("{\n\t.reg .pred P1;\n\t"
                     "W%=:\n\t"
                     "mbarrier.try_wait.parity.acquire.cta.shared::cta.b64 P1, [%0], %1, 0x989680;\n\t"
                     "@P1 bra.uni D%=;\n\t"
                     "bra.uni W%=;\n\t"
                     "D%=:\n\t}"
                     :: "r"(mbar), "r"(parity) : "memory");
    }
}

__global__ __launch_bounds__(BLOCK, 6)
void triplet_fused_kernel(const float* __restrict__ sim,
                          const int* __restrict__ targets,
                          const int* __restrict__ idx,
                          float* __restrict__ out,
                          int n) {
    __shared__ __align__(128) float s_buf[CHUNKS][CHUNK_FLOATS];   // 32 KB
    __shared__ __align__(8) unsigned long long s_mbar[CHUNKS];
    __shared__ float s_pos[BLOCK / 32];
    __shared__ float s_neg[BLOCK / 32];
    __shared__ unsigned int s_is_last;

    const int tid = threadIdx.x;
    const int wid = tid >> 5;
    const int lid = tid & 31;
    const int row = blockIdx.x;

    const int my_t = targets[row];
    const int self_col = idx[row];
    const float* __restrict__ rp = sim + (size_t)self_col * (size_t)n;

    // Init barriers, then tid0 fires all 8 bulk copies (whole row prefetch).
    if (tid == 0) {
        #pragma unroll
        for (int c = 0; c < CHUNKS; c++)
            mbar_init(smem_addr_u32(&s_mbar[c]), 1);
    }
    __syncthreads();
    if (tid == 0) {
        #pragma unroll
        for (int c = 0; c < CHUNKS; c++) {
            const uint32_t mb = smem_addr_u32(&s_mbar[c]);
            mbar_expect_tx(mb, CHUNK_BYTES);
            bulk_g2s(smem_addr_u32(&s_buf[c][0]), rp + c * CHUNK_FLOATS,
                     CHUNK_BYTES, mb);
        }
    }

    // Mask setup overlaps with the bulk copies.
    unsigned int mp = g_mask32[my_t * BLOCK + tid];   // pos bits (32 cols/thread)
    // Clear self bit (same-class by construction, so only pos needs it).
    if (((self_col >> 2) & (BLOCK - 1)) == tid) {
        const int bit = ((self_col >> 10) << 2) | (self_col & 3);
        mp &= ~(1u << bit);
    }
    const unsigned int mn = ~(g_mask32[my_t * BLOCK + tid]);  // neg bits

    float pos =  FLT_MAX;
    float neg = -FLT_MAX;

    #pragma unroll
    for (int c = 0; c < CHUNKS; c++) {
        mbar_wait(smem_addr_u32(&s_mbar[c]), 0);
        const float4 v = *reinterpret_cast<const float4*>(&s_buf[c][tid * 4]);
        const unsigned int np = mp >> (c * 4);
        const unsigned int nn = mn >> (c * 4);
        if (np & 1u) pos = fminf(pos, v.x);
        if (nn & 1u) neg = fmaxf(neg, v.x);
        if (np & 2u) pos = fminf(pos, v.y);
        if (nn & 2u) neg = fmaxf(neg, v.y);
        if (np & 4u) pos = fminf(pos, v.z);
        if (nn & 4u) neg = fmaxf(neg, v.z);
        if (np & 8u) pos = fminf(pos, v.w);
        if (nn & 8u) neg = fmaxf(neg, v.w);
    }

    // Warp reduction.
    #pragma unroll
    for (int off = 16; off > 0; off >>= 1) {
        pos = fminf(pos, __shfl_xor_sync(0xFFFFFFFFu, pos, off));
        neg = fmaxf(neg, __shfl_xor_sync(0xFFFFFFFFu, neg, off));
    }
    if (lid == 0) { s_pos[wid] = pos; s_neg[wid] = neg; }
    __syncthreads();

    // Thread 0: cross-warp combine in fixed order, write loss, arrive.
    if (tid == 0) {
        float p = s_pos[0], g = s_neg[0];
        #pragma unroll
        for (int w = 1; w < BLOCK / 32; w++) {
            p = fminf(p, s_pos[w]);
            g = fmaxf(g, s_neg[w]);
        }
        g_block_sum[row] = fmaxf(g - p + 0.1f, 0.0f);
        __threadfence();
        unsigned int prev = atomicInc(&g_done_count, GRID - 1);
        s_is_last = (prev == GRID - 1) ? 1u : 0u;
    }
    __syncthreads();

    // Last block: deterministic fixed-order mean over 8192 losses.
    if (s_is_last) {
        __shared__ float s_sum[BLOCK / 32];
        const float4* bp = reinterpret_cast<const float4*>(g_block_sum);
        float acc = 0.0f;
        #pragma unroll
        for (int c = 0; c < 8; c++) {                // 8192/4/256 = 8
            float4 a = __ldcg(bp + c * BLOCK + tid);
            acc += (a.x + a.y) + (a.z + a.w);
        }
        #pragma unroll
        for (int off = 16; off > 0; off >>= 1)
            acc += __shfl_xor_sync(0xFFFFFFFFu, acc, off);
        if (lid == 0) s_sum[wid] = acc;
        __syncthreads();
        if (wid == 0) {
            acc = (lid < BLOCK / 32) ? s_sum[lid] : 0.0f;
            #pragma unroll
            for (int off = 4; off > 0; off >>= 1)
                acc += __shfl_xor_sync(0xFFFFFFFFu, acc, off);
            if (lid == 0) out[0] = acc / (float)MAX_N;
        }
    }
}

extern "C" void kernel_launch(void* const* d_in, const int* in_sizes, int n_in,
                              void* d_out, int out_size) {
    const float* sim     = (const float*)d_in[0];
    const int*   targets = (const int*)d_in[1];
    const int*   idx     = (const int*)d_in[2];
    float* out = (float*)d_out;

    const int n = in_sizes[1];   // 8192

    build_masks_kernel<<<N_CLASSES, BLOCK>>>(targets);
    triplet_fused_kernel<<<GRID, BLOCK>>>(sim, targets, idx, out, n);
}

// round 9
// speedup vs baseline: 1.0394x; 1.0394x over previous
#include <cuda_runtime.h>
#include <cuda_bf16.h>
#include <float.h>

#define MAX_N 8192
#define BLOCK 256
#define ROWS_PER_BLOCK 4                      // 8 warps, 2 per row
#define GRID (MAX_N / ROWS_PER_BLOCK)         // 2048

__device__ float        g_block_sum[GRID];
__device__ unsigned int g_done_count = 0;     // self-resets via atomicInc wrap

__global__ __launch_bounds__(BLOCK, 8)        // regs<=32 -> 8 blocks/SM
void triplet_fused_kernel(const float* __restrict__ sim,
                          const int* __restrict__ targets,
                          const int* __restrict__ idx,
                          float* __restrict__ out,
                          int n) {
    __shared__ float s_pos[BLOCK / 32];
    __shared__ float s_neg[BLOCK / 32];
    __shared__ float s_loss[ROWS_PER_BLOCK];
    __shared__ unsigned int s_is_last;

    const int tid  = threadIdx.x;
    const int wid  = tid >> 5;
    const int lid  = tid & 31;
    const int rloc = wid >> 1;
    const int half = wid & 1;

    const int row = blockIdx.x * ROWS_PER_BLOCK + rloc;
    const int my_t = targets[row];
    const int self_col = idx[row];
    const float* __restrict__ rp = sim + (size_t)self_col * (size_t)n;
    const int4* __restrict__ tp = reinterpret_cast<const int4*>(targets);

    const int jbeg = half * (n >> 1);         // 0 or 4096

    float pos =  FLT_MAX;
    float neg = -FLT_MAX;

    // Warp streams its 16 KB half-row; 4 independent LDG.128 in flight.
    // Self-column handled by a single hoisted range check per float4 group:
    // the expensive per-element self compare runs only for the one group
    // (one lane, one iteration per row) that actually contains it.
    #pragma unroll 4
    for (int it = 0; it < (n / 2) / (32 * 4); it++) {
        const int j = jbeg + it * 128 + lid * 4;
        const float4 v = __ldcs(reinterpret_cast<const float4*>(rp + j));
        const int4   t = tp[j >> 2];

        if ((unsigned)(self_col - j) < 4u) {
            // Rare path: group contains the self column.
            if (t.x == my_t) { if (j + 0 != self_col) pos = fminf(pos, v.x); }
            else             { neg = fmaxf(neg, v.x); }
            if (t.y == my_t) { if (j + 1 != self_col) pos = fminf(pos, v.y); }
            else             { neg = fmaxf(neg, v.y); }
            if (t.z == my_t) { if (j + 2 != self_col) pos = fminf(pos, v.z); }
            else             { neg = fmaxf(neg, v.z); }
            if (t.w == my_t) { if (j + 3 != self_col) pos = fminf(pos, v.w); }
            else             { neg = fmaxf(neg, v.w); }
        } else {
            // Fast path: no self in this group -> 1 compare per element.
            if (t.x == my_t) pos = fminf(pos, v.x); else neg = fmaxf(neg, v.x);
            if (t.y == my_t) pos = fminf(pos, v.y); else neg = fmaxf(neg, v.y);
            if (t.z == my_t) pos = fminf(pos, v.z); else neg = fmaxf(neg, v.z);
            if (t.w == my_t) pos = fminf(pos, v.w); else neg = fmaxf(neg, v.w);
        }
    }

    // Warp reduction.
    #pragma unroll
    for (int off = 16; off > 0; off >>= 1) {
        pos = fminf(pos, __shfl_xor_sync(0xFFFFFFFFu, pos, off));
        neg = fmaxf(neg, __shfl_xor_sync(0xFFFFFFFFu, neg, off));
    }
    if (lid == 0) { s_pos[wid] = pos; s_neg[wid] = neg; }
    __syncthreads();

    // Combine half-row partials; fixed order -> deterministic.
    if (tid < ROWS_PER_BLOCK) {
        const int w0 = tid * 2;
        const float p = fminf(s_pos[w0], s_pos[w0 + 1]);
        const float g = fmaxf(s_neg[w0], s_neg[w0 + 1]);
        s_loss[tid] = fmaxf(g - p + 0.1f, 0.0f);
    }
    __syncthreads();

    if (tid == 0) {
        float bs = 0.0f;
        #pragma unroll
        for (int r = 0; r < ROWS_PER_BLOCK; r++) bs += s_loss[r];
        g_block_sum[blockIdx.x] = bs;
        __threadfence();
        unsigned int prev = atomicInc(&g_done_count, GRID - 1);
        s_is_last = (prev == GRID - 1) ? 1u : 0u;
    }
    __syncthreads();

    // Last block: deterministic fixed-tree mean over 2048 partials.
    if (s_is_last) {
        __shared__ float s_sum[BLOCK / 32];
        const float4* bp = reinterpret_cast<const float4*>(g_block_sum);
        float4 a = __ldcg(bp + tid);
        float4 b = __ldcg(bp + tid + 256);
        float acc = ((a.x + a.y) + (a.z + a.w)) + ((b.x + b.y) + (b.z + b.w));
        #pragma unroll
        for (int off = 16; off > 0; off >>= 1)
            acc += __shfl_xor_sync(0xFFFFFFFFu, acc, off);
        if (lid == 0) s_sum[wid] = acc;
        __syncthreads();
        if (wid == 0) {
            acc = (lid < BLOCK / 32) ? s_sum[lid] : 0.0f;
            #pragma unroll
            for (int off = 4; off > 0; off >>= 1)
                acc += __shfl_xor_sync(0xFFFFFFFFu, acc, off);
            if (lid == 0) out[0] = acc / (float)n;
        }
    }
}

extern "C" void kernel_launch(void* const* d_in, const int* in_sizes, int n_in,
                              void* d_out, int out_size) {
    const float* sim     = (const float*)d_in[0];
    const int*   targets = (const int*)d_in[1];
    const int*   idx     = (const int*)d_in[2];
    float* out = (float*)d_out;

    const int n = in_sizes[1];   // 8192

    triplet_fused_kernel<<<GRID, BLOCK>>>(sim, targets, idx, out, n);
}

// round 10
// speedup vs baseline: 1.0597x; 1.0195x over previous
#include <cuda_runtime.h>
#include <cuda_bf16.h>
#include <float.h>

#define MAX_N 8192
#define BLOCK 256
#define ROWS_PER_BLOCK 8   // one row per warp
#define GRID (MAX_N / ROWS_PER_BLOCK)   // 1024 -> single wave at 7 blocks/SM

__device__ float        g_block_sum[GRID];
__device__ unsigned int g_done_count = 0;   // self-resets via atomicInc wrap

__global__ __launch_bounds__(BLOCK, 7)      // regs<=36 -> 7 blocks/SM -> 1 wave
void triplet_fused_kernel(const float* __restrict__ sim,
                          const int* __restrict__ targets,
                          const int* __restrict__ idx,
                          float* __restrict__ out,
                          int n) {
    __shared__ float s_loss[ROWS_PER_BLOCK];
    __shared__ unsigned int s_is_last;

    const int tid = threadIdx.x;
    const int wid = tid >> 5;
    const int lid = tid & 31;

    const int row = blockIdx.x * ROWS_PER_BLOCK + wid;
    const int my_t = targets[row];
    const int self_col = idx[row];
    const float* __restrict__ rp = sim + (size_t)self_col * (size_t)n;
    const int4* __restrict__ tp = reinterpret_cast<const int4*>(targets);

    float pos =  FLT_MAX;
    float neg = -FLT_MAX;

    // Warp streams its 32 KB row (evict-first); targets are L1-resident.
    // Unroll 4 -> 4 independent LDG.128 pairs in flight per thread.
    #pragma unroll 4
    for (int it = 0; it < n / (32 * 4); it++) {
        const int j = it * 128 + lid * 4;
        const float4 v = __ldcs(reinterpret_cast<const float4*>(rp + j));
        const int4   t = tp[j >> 2];

        if (t.x == my_t) { if (j + 0 != self_col) pos = fminf(pos, v.x); }
        else             { neg = fmaxf(neg, v.x); }
        if (t.y == my_t) { if (j + 1 != self_col) pos = fminf(pos, v.y); }
        else             { neg = fmaxf(neg, v.y); }
        if (t.z == my_t) { if (j + 2 != self_col) pos = fminf(pos, v.z); }
        else             { neg = fmaxf(neg, v.z); }
        if (t.w == my_t) { if (j + 3 != self_col) pos = fminf(pos, v.w); }
        else             { neg = fmaxf(neg, v.w); }
    }

    // Warp reduction.
    #pragma unroll
    for (int off = 16; off > 0; off >>= 1) {
        pos = fminf(pos, __shfl_xor_sync(0xFFFFFFFFu, pos, off));
        neg = fmaxf(neg, __shfl_xor_sync(0xFFFFFFFFu, neg, off));
    }
    if (lid == 0) s_loss[wid] = fmaxf(neg - pos + 0.1f, 0.0f);
    __syncthreads();

    // One thread sums the block's 8 losses in FIXED order -> deterministic.
    if (tid == 0) {
        float bs = 0.0f;
        #pragma unroll
        for (int w = 0; w < ROWS_PER_BLOCK; w++) bs += s_loss[w];
        g_block_sum[blockIdx.x] = bs;
        __threadfence();
        unsigned int prev = atomicInc(&g_done_count, GRID - 1);
        s_is_last = (prev == GRID - 1) ? 1u : 0u;
    }
    __syncthreads();

    // Last block reduces the 1024 partials in fixed tree order (deterministic).
    if (s_is_last) {
        __shared__ float s_sum[BLOCK / 32];
        const float4* bp = reinterpret_cast<const float4*>(g_block_sum);
        float4 a = __ldcg(bp + tid);
        float acc = (a.x + a.y) + (a.z + a.w);
        #pragma unroll
        for (int off = 16; off > 0; off >>= 1)
            acc += __shfl_xor_sync(0xFFFFFFFFu, acc, off);
        if (lid == 0) s_sum[wid] = acc;
        __syncthreads();
        if (wid == 0) {
            acc = (lid < BLOCK / 32) ? s_sum[lid] : 0.0f;
            #pragma unroll
            for (int off = 4; off > 0; off >>= 1)
                acc += __shfl_xor_sync(0xFFFFFFFFu, acc, off);
            if (lid == 0) out[0] = acc / (float)n;
        }
    }
}

extern "C" void kernel_launch(void* const* d_in, const int* in_sizes, int n_in,
                              void* d_out, int out_size) {
    const float* sim     = (const float*)d_in[0];
    const int*   targets = (const int*)d_in[1];
    const int*   idx     = (const int*)d_in[2];
    float* out = (float*)d_out;

    const int n = in_sizes[1];   // 8192

    triplet_fused_kernel<<<GRID, BLOCK>>>(sim, targets, idx, out, n);
}